// round 15
// baseline (speedup 1.0000x reference)
#include <cuda_runtime.h>
#include <math.h>

#define Bn 64
#define Tn 800
#define Un 64
#define Nn 64
#define Kn 10
#define Hn 512
#define On 121
#define G4H 2048
#define HB (Hn*Bn)      /* 32768 */
#define NB (Nn*Bn)      /* 4096  */
#define NGEMM 128
#define NATT  16
#define NCTA 128
#define NTHR 1024

typedef unsigned long long ull;

// Eigen/XLA-CPU pexp clamps its argument at ln(2^-126); replicate so the
// underflow tail ties bit-exactly (argmax -> 0) like the reference.
#define EXP_LO (-87.33654f)

// scan01 SMEM layout (floats)
#define SW0_OFF 0                   /* 579*16  = 9264  */
#define SW1_OFF 9264                /* 1091*16 = 17456 */
#define SPA_OFF (9264+17456)        /* 26720 */
#define SZ_OFF  (SPA_OFF + 16384)   /* 43104 */
#define SMEM_A ((SZ_OFF + 1024) * 4)     /* 176512 B */

// scan2 SMEM layout
#define SP2_OFF 17456
#define SZ2_OFF (SP2_OFF + 16384)
#define SMEM_S2 ((SZ2_OFF + 1024) * 4)   /* 139456 B */

// ---------------- device scratch (static, no allocations) ----------------
__device__ __align__(16) float g_h0[Tn*HB];          // [t][d][b]
__device__ __align__(16) float g_h1[Tn*HB];
__device__ __align__(16) float g_h2[Tn*HB];
__device__ __align__(16) float g_w [Tn*NB];          // [t][n][b]
__device__ __align__(16) float g_xT[Tn*3*Bn];        // [t][dim][b]
__device__ unsigned g_barc[4];                       // monotone barrier counters

// ---------------- fp32x2 helpers -----------------------------------------
__device__ __forceinline__ void fma2(ull &acc, ull a, ull b) {
    asm("fma.rn.f32x2 %0, %1, %2, %0;" : "+l"(acc) : "l"(a), "l"(b));
}
__device__ __forceinline__ void add2(ull &a, ull b) {
    asm("add.rn.f32x2 %0, %0, %1;" : "+l"(a) : "l"(b));
}
__device__ __forceinline__ ull dup2(float w) {
    ull r; asm("mov.b64 %0, {%1, %1};" : "=l"(r) : "f"(w)); return r;
}
__device__ __forceinline__ void unpack2(ull v, float &lo, float &hi) {
    asm("mov.b64 {%0, %1}, %2;" : "=f"(lo), "=f"(hi) : "l"(v));
}

// 8 cols x 4 batches accumulate: acc[2j]=(b0,b1), acc[2j+1]=(b2,b3) for col j
__device__ __forceinline__ void mac8(ull* acc, ulonglong2 in, float4 w0, float4 w1) {
    fma2(acc[0],  in.x, dup2(w0.x)); fma2(acc[1],  in.y, dup2(w0.x));
    fma2(acc[2],  in.x, dup2(w0.y)); fma2(acc[3],  in.y, dup2(w0.y));
    fma2(acc[4],  in.x, dup2(w0.z)); fma2(acc[5],  in.y, dup2(w0.z));
    fma2(acc[6],  in.x, dup2(w0.w)); fma2(acc[7],  in.y, dup2(w0.w));
    fma2(acc[8],  in.x, dup2(w1.x)); fma2(acc[9],  in.y, dup2(w1.x));
    fma2(acc[10], in.x, dup2(w1.y)); fma2(acc[11], in.y, dup2(w1.y));
    fma2(acc[12], in.x, dup2(w1.z)); fma2(acc[13], in.y, dup2(w1.z));
    fma2(acc[14], in.x, dup2(w1.w)); fma2(acc[15], in.y, dup2(w1.w));
}

// 16 distinct rows per warp, 4-deep LDG prefetch (32-warp CTA variant).
__device__ __forceinline__ void gemm_rows16(ull* acc, const float* __restrict__ gp,
                                            const float* __restrict__ wp) {
    ulonglong2 ib[4];
    #pragma unroll
    for (int i = 0; i < 4; ++i)
        ib[i] = *reinterpret_cast<const ulonglong2*>(gp + (size_t)i*64);
    #pragma unroll
    for (int c = 0; c < 4; ++c) {
        #pragma unroll
        for (int i = 0; i < 4; ++i) {
            int r = c*4 + i;
            float4 w0 = *reinterpret_cast<const float4*>(wp + r*16);
            float4 w1 = *reinterpret_cast<const float4*>(wp + r*16 + 4);
            ulonglong2 in = ib[i];
            if (c < 3)
                ib[i] = *reinterpret_cast<const ulonglong2*>(gp + (size_t)(r+4)*64);
            mac8(acc, in, w0, w1);
        }
    }
}

__device__ __forceinline__ void gemm_rowsN(ull* acc, const float* __restrict__ gp,
                                           const float* __restrict__ wp, int n) {
    #pragma unroll 4
    for (int r = 0; r < n; ++r) {
        ulonglong2 in = *reinterpret_cast<const ulonglong2*>(gp + (size_t)r*64);
        float4 w0 = *reinterpret_cast<const float4*>(wp + r*16);
        float4 w1 = *reinterpret_cast<const float4*>(wp + r*16 + 4);
        mac8(acc, in, w0, w1);
    }
}

// two-round partial store: warps 0..15 store slice warp, warps 16..31 add in.
// sP layout: [slice 16][col 16][b 64]
__device__ __forceinline__ void store_partials2(float* sP, int warp, int ch, int bg,
                                                const ull* acc) {
    float* pp = sP + (warp & 15)*1024 + (ch*8)*64 + bg*4;
    if (warp < 16) {
        #pragma unroll
        for (int j = 0; j < 8; ++j)
            *reinterpret_cast<ulonglong2*>(pp + j*64) =
                make_ulonglong2(acc[2*j], acc[2*j+1]);
    }
    __syncthreads();
    if (warp >= 16) {
        #pragma unroll
        for (int j = 0; j < 8; ++j) {
            ulonglong2 m = *reinterpret_cast<ulonglong2*>(pp + j*64);
            add2(m.x, acc[2*j]); add2(m.y, acc[2*j+1]);
            *reinterpret_cast<ulonglong2*>(pp + j*64) = m;
        }
    }
    __syncthreads();
}

// 512-thread f32x2 tree reduce over 16 slices (tree as in scalar reduce16)
__device__ __forceinline__ void reduce_pairs(const float* sP, float* sZ, int tid) {
    int col = tid >> 5, b2 = tid & 31;
    const float* base = sP + col*64 + b2*2;
    ull v[16];
    #pragma unroll
    for (int k = 0; k < 16; ++k)
        v[k] = *reinterpret_cast<const ull*>(base + k*1024);
    ull s0 = v[0];  add2(s0, v[1]);  ull t0 = v[8];  add2(t0, v[9]);  add2(s0, t0);
    ull s1 = v[2];  add2(s1, v[3]);  ull t1 = v[10]; add2(t1, v[11]); add2(s1, t1);
    ull s2 = v[4];  add2(s2, v[5]);  ull t2 = v[12]; add2(t2, v[13]); add2(s2, t2);
    ull s3 = v[6];  add2(s3, v[7]);  ull t3 = v[14]; add2(t3, v[15]); add2(s3, t3);
    add2(s0, s1); add2(s2, s3); add2(s0, s2);
    *reinterpret_cast<ull*>(sZ + col*64 + b2*2) = s0;
}

// fast gates (~1e-6 rel err)
__device__ __forceinline__ float sigf2(float x) {
    return __fdividef(1.f, 1.f + __expf(-x));
}
__device__ __forceinline__ float tanhf2(float x) {
    return 1.f - __fdividef(2.f, __expf(2.f*x) + 1.f);
}

// reduce (512 thr) + gates (256 thr) + h store
__device__ __forceinline__ void reduce_gates(
    float* sP, float* sZ, int tid, const float* sbL,
    float& creg, float* hout, int u0)
{
    if (tid < 512) reduce_pairs(sP, sZ, tid);
    __syncthreads();
    if (tid < 256) {
        int uuR = tid >> 6, bR = tid & 63;
        float z[4];
        #pragma unroll
        for (int g = 0; g < 4; ++g)
            z[g] = sbL[uuR*4 + g] + sZ[(uuR*4 + g)*64 + bR];
        float cn = sigf2(z[1])*creg + sigf2(z[0])*tanhf2(z[2]);
        creg = cn;
        hout[(u0+uuR)*64 + bR] = sigf2(z[3])*tanhf2(cn);
    }
    __syncthreads();
}

// ---------------- release/acquire barrier primitives ---------------------
__device__ __forceinline__ void bar_arrive(int slot) {
    asm volatile("red.release.gpu.global.add.u32 [%0], 1;"
                 :: "l"(g_barc + slot) : "memory");
}
__device__ __forceinline__ void bar_wait_ge(int slot, unsigned target) {
    unsigned v;
    do {
        asm volatile("ld.acquire.gpu.global.u32 %0, [%1];"
                     : "=r"(v) : "l"(g_barc + slot) : "memory");
    } while (v < target);
}

// ---------------- init: barrier vars + stroke transpose ------------------
__global__ void k_init(const float* __restrict__ strokes) {
    int i = blockIdx.x * blockDim.x + threadIdx.x;
    int stride = gridDim.x * blockDim.x;
    for (int j = i; j < Tn*3*Bn; j += stride) {
        int t = j / 192, rem = j % 192, dim = rem / 64, b = rem & 63;
        g_xT[j] = strokes[b*(Tn*3) + t*3 + dim];
    }
    if (i < 4) g_barc[i] = 0u;
}

// =========================================================================
// Fused L0+L1 scan + attention.  144 CTAs x 1024 thr persistent.
//   CTA 0..127  : GEMM role. Tick t: L0 step t, then L1 step t-1.
//                 warp w covers rows [16w,16w+16); w-rows 2/warp; x warp31.
//   CTA 128..143: attention role (4 batches; threads >=512 only sync).
// Slots: 0 = h0 (128/tick), 1 = w (16/tick), 2 = h1 (128/tick).
// =========================================================================
__global__ void __launch_bounds__(NTHR, 1)
k_scan01(const float* __restrict__ trans,
         const float* __restrict__ W0, const float* __restrict__ R0,
         const float* __restrict__ b0, const float* __restrict__ Wd,
         const float* __restrict__ bd,
         const float* __restrict__ W1, const float* __restrict__ R1,
         const float* __restrict__ b1, float* __restrict__ attOut)
{
    extern __shared__ float sm[];
    const int tid  = threadIdx.x;
    const int lane = tid & 31;
    const int warp = tid >> 5;

    if (blockIdx.x < NGEMM) {
        // ================= GEMM role =================
        float* sW0 = sm + SW0_OFF;
        float* sW1 = sm + SW1_OFF;
        float* sP  = sm + SPA_OFF;
        float* sZ  = sm + SZ_OFF;
        __shared__ float sb[32];

        const int bg = lane & 15;
        const int ch = lane >> 4;
        const int u0 = blockIdx.x * 4;

        for (int idx = tid; idx < 579*16; idx += NTHR) {
            int r = idx >> 4, c = idx & 15;
            int col = (c & 3) * 512 + u0 + (c >> 2);
            float v;
            if (r < 512)      v = R0[r*G4H + col];
            else if (r < 576) v = W0[(3 + r - 512)*G4H + col];
            else              v = W0[(r - 576)*G4H + col];
            sW0[idx] = v;
        }
        for (int idx = tid; idx < 1091*16; idx += NTHR) {
            int r = idx >> 4, c = idx & 15;
            int col = (c & 3) * 512 + u0 + (c >> 2);
            float v;
            if (r < 512)       v = R1[r*G4H + col];
            else if (r < 1024) v = W1[(r - 512)*G4H + col];
            else if (r < 1088) v = W1[(512 + r - 1024)*G4H + col];
            else               v = W1[(576 + r - 1088)*G4H + col];
            sW1[idx] = v;
        }
        if (tid < 16) {
            sb[tid]      = b0[(tid & 3) * 512 + u0 + (tid >> 2)];
            sb[16 + tid] = b1[(tid & 3) * 512 + u0 + (tid >> 2)];
        }
        __syncthreads();

        float c0 = 0.f, c1 = 0.f;
        for (int t = 0; t <= Tn; ++t) {
            // ---------- L0 step t ----------
            if (t < Tn) {
                ull acc[16];
                #pragma unroll
                for (int i = 0; i < 16; ++i) acc[i] = 0ull;
                if (t > 0)
                    gemm_rows16(acc, g_h0 + (size_t)(t-1)*HB + (warp*16)*64 + bg*4,
                                sW0 + (warp*16)*16 + ch*8);
                if (warp == 31)
                    gemm_rowsN(acc, g_xT + (size_t)t*192 + bg*4,
                               sW0 + 576*16 + ch*8, 3);
                if (tid == 0) bar_wait_ge(1, (unsigned)t * NATT);
                __syncthreads();
                if (t > 0)
                    gemm_rowsN(acc, g_w + (size_t)(t-1)*NB + (warp*2)*64 + bg*4,
                               sW0 + (512 + warp*2)*16 + ch*8, 2);
                store_partials2(sP, warp, ch, bg, acc);
                reduce_gates(sP, sZ, tid, sb, c0, g_h0 + (size_t)t*HB, u0);
                if (tid == 0) bar_arrive(0);     // S1: h0[t]
            } else {
                if (tid == 0) bar_wait_ge(1, (unsigned)Tn * NATT);
                __syncthreads();
            }

            if (t == 0) {
                // no L1 yet: expose the S1 wait once
                if (tid == 0) bar_wait_ge(0, (unsigned)NGEMM);
                __syncthreads();
                continue;
            }

            // ---------- L1 step t-1 (hides S1 + S3 rounds) ----------
            {
                const int s = t - 1;
                ull acc[16];
                #pragma unroll
                for (int i = 0; i < 16; ++i) acc[i] = 0ull;
                gemm_rows16(acc, g_h0 + (size_t)s*HB + (warp*16)*64 + bg*4,
                            sW1 + (512 + warp*16)*16 + ch*8);
                gemm_rowsN(acc, g_w + (size_t)s*NB + (warp*2)*64 + bg*4,
                           sW1 + (1024 + warp*2)*16 + ch*8, 2);
                if (warp == 31)
                    gemm_rowsN(acc, g_xT + (size_t)s*192 + bg*4,
                               sW1 + 1088*16 + ch*8, 3);
                // both chip-wide waits posted behind the ff-GEMM above
                if (tid == 0) {
                    if (t < Tn) bar_wait_ge(0, (unsigned)(t+1) * NGEMM);
                    if (s > 0)  bar_wait_ge(2, (unsigned)s * NGEMM);
                }
                __syncthreads();
                if (s > 0)
                    gemm_rows16(acc, g_h1 + (size_t)(s-1)*HB + (warp*16)*64 + bg*4,
                                sW1 + (warp*16)*16 + ch*8);
                store_partials2(sP, warp, ch, bg, acc);
                reduce_gates(sP, sZ, tid, sb + 16, c1, g_h1 + (size_t)s*HB, u0);
                if (tid == 0) bar_arrive(2);     // S3: h1[s]
            }
        }
    } else {
        // ================= attention role =================
        float* sWd = sm;                    // 512*30 = 15360
        float* sTr = sm + 15360;            // 4*64*64 = 16384
        __shared__ float sPart[16*30*4];    // [w 16][c 30][b 4]
        __shared__ float sbd[30];
        __shared__ float sy[4*32];
        __shared__ float skap[4*16];
        __shared__ float swf[4*72];

        const int bb = (blockIdx.x - NGEMM) * 4;

        for (int idx = tid; idx < 512*30; idx += NTHR) sWd[idx] = Wd[idx];
        for (int idx = tid; idx < 16384; idx += NTHR) {
            int b_ = idx >> 12;
            sTr[idx] = trans[(bb + b_)*(Un*Nn) + (idx & 4095)];
        }
        if (tid < 30) sbd[tid] = bd[tid];
        if (tid < 64) skap[tid] = 0.f;
        __syncthreads();

        for (int t = 0; t < Tn; ++t) {
            if (tid == 0) bar_wait_ge(0, (unsigned)(t+1) * NGEMM);
            __syncthreads();

            // Wd matvec: warps 0..15, coalesced broadcast h0 reads
            if (warp < 16 && lane < 30) {
                const float* hp = g_h0 + (size_t)t*HB + bb;
                const int d0 = warp*32;
                const float* wp = sWd + d0*30 + lane;
                float a0 = 0.f, a1 = 0.f, a2 = 0.f, a3 = 0.f;
                float4 hbuf[4];
                #pragma unroll
                for (int i = 0; i < 4; ++i)
                    hbuf[i] = *reinterpret_cast<const float4*>(hp + (d0+i)*64);
                #pragma unroll
                for (int r = 0; r < 32; ++r) {
                    float4 h = hbuf[r & 3];
                    if (r + 4 < 32)
                        hbuf[r & 3] = *reinterpret_cast<const float4*>(hp + (d0+r+4)*64);
                    float wv = wp[r*30];
                    a0 += h.x*wv; a1 += h.y*wv; a2 += h.z*wv; a3 += h.w*wv;
                }
                float* pp = sPart + (warp*30 + lane)*4;
                pp[0] = a0; pp[1] = a1; pp[2] = a2; pp[3] = a3;
            }
            __syncthreads();

            if (warp < 4) {
                int b_ = warp;
                if (lane < 30) {
                    float y = sbd[lane];
                    #pragma unroll
                    for (int s = 0; s < 16; ++s)
                        y += sPart[(s*30 + lane)*4 + b_];
                    sy[b_*32 + lane] = expf(y);
                }
                __syncwarp();
                if (lane < Kn) skap[b_*16 + lane] += sy[b_*32 + 20 + lane];
                __syncwarp();
            }
            __syncthreads();

            if (tid < 512) {
                int b_ = tid >> 7, u = tid & 127;
                if (u < Un + 1) {
                    float s = 0.f;
                    #pragma unroll
                    for (int k = 0; k < Kn; ++k) {
                        float dd  = skap[b_*16 + k] - (float)(u + 1);
                        float arg = -sy[b_*32 + 10 + k] * dd * dd;
                        if (arg < EXP_LO) arg = EXP_LO;   // Eigen pexp clamp
                        s += sy[b_*32 + k] * expf(arg);
                    }
                    swf[b_*72 + u] = s;
                }
            }
            __syncthreads();

            if (tid < 512) {
                int b_ = tid >> 7, n = tid & 127;
                if (n < Nn) {
                    const float* wf = swf + b_*72;
                    const float* tp = sTr + b_*4096 + n;
                    float acc2 = 0.f;
                    #pragma unroll 8
                    for (int u = 0; u < Un; ++u)
                        acc2 += wf[u] * tp[u*64];
                    g_w[(size_t)t*NB + n*64 + bb + b_] = acc2;
                } else if (n == 64) {
                    const float* wf = swf + b_*72;
                    float best = wf[0]; int bi = 0;
                    #pragma unroll 8
                    for (int u = 1; u < Un + 1; ++u)
                        if (wf[u] > best) { best = wf[u]; bi = u; }
                    attOut[(bb + b_)*Tn + t] = (float)bi;
                }
            }
            __syncthreads();
            if (tid == 0) bar_arrive(1);   // S2: w[t]
        }
    }
}

// =========================================================================
// L2 scan: 128 CTAs x 1024 thr. ff of t+1 posted between arrive and wait.
// =========================================================================
__global__ void __launch_bounds__(NTHR, 1)
k_scan2(const float* __restrict__ R, const float* __restrict__ W,
        const float* __restrict__ bias)
{
    extern __shared__ float sm[];
    float* sW = sm;                  // 1091*16 = 17456
    float* sP = sm + SP2_OFF;
    float* sZ = sm + SZ2_OFF;
    __shared__ float sb[16];

    const float* hin = g_h1;
    float* hseq      = g_h2;
    const int slot = 3;
    const int tid  = threadIdx.x;
    const int lane = tid & 31;
    const int warp = tid >> 5;
    const int bg   = lane & 15;
    const int ch   = lane >> 4;
    const int u0   = blockIdx.x * 4;

    for (int idx = tid; idx < 1091*16; idx += NTHR) {
        int r = idx >> 4, c = idx & 15;
        int col = (c & 3) * 512 + u0 + (c >> 2);
        float v;
        if (r < 512)       v = R[r*G4H + col];
        else if (r < 1024) v = W[(r - 512)*G4H + col];
        else if (r < 1088) v = W[(512 + r - 1024)*G4H + col];
        else               v = W[(576 + r - 1088)*G4H + col];
        sW[idx] = v;
    }
    if (tid < 16) sb[tid] = bias[(tid & 3) * 512 + u0 + (tid >> 2)];
    float creg = 0.f;
    __syncthreads();

    ull acc[16];
    #pragma unroll
    for (int i = 0; i < 16; ++i) acc[i] = 0ull;
    gemm_rows16(acc, hin + (warp*16)*64 + bg*4, sW + (512 + warp*16)*16 + ch*8);
    gemm_rowsN(acc, g_w + (warp*2)*64 + bg*4, sW + (1024 + warp*2)*16 + ch*8, 2);
    if (warp == 31)
        gemm_rowsN(acc, g_xT + bg*4, sW + 1088*16 + ch*8, 3);

    for (int t = 0; t < Tn; ++t) {
        if (t > 0)
            gemm_rows16(acc, hseq + (size_t)(t-1)*HB + (warp*16)*64 + bg*4,
                        sW + (warp*16)*16 + ch*8);

        store_partials2(sP, warp, ch, bg, acc);
        reduce_gates(sP, sZ, tid, sb, creg, hseq + (size_t)t*HB, u0);
        if (tid == 0) bar_arrive(slot);

        #pragma unroll
        for (int i = 0; i < 16; ++i) acc[i] = 0ull;
        if (t < Tn - 1) {
            gemm_rows16(acc, hin + (size_t)(t+1)*HB + (warp*16)*64 + bg*4,
                        sW + (512 + warp*16)*16 + ch*8);
            gemm_rowsN(acc, g_w + (size_t)(t+1)*NB + (warp*2)*64 + bg*4,
                       sW + (1024 + warp*2)*16 + ch*8, 2);
            if (warp == 31)
                gemm_rowsN(acc, g_xT + (size_t)(t+1)*192 + bg*4,
                           sW + 1088*16 + ch*8, 3);
        }
        if (tid == 0) bar_wait_ge(slot, (unsigned)(t+1) * NCTA);
        __syncthreads();
    }
}

// =========================================================================
// Output GEMM: out[b][t][o] = [h0,h1,h2][t] @ Wo + bo   (grid = 800 CTAs)
// =========================================================================
__global__ void __launch_bounds__(256)
k_out(const float* __restrict__ Wo, const float* __restrict__ bo,
      float* __restrict__ out)
{
    const int t = blockIdx.x;
    const int tid = threadIdx.x;
    const int c = tid & 127;
    const int bh = tid >> 7;
    if (c >= On) return;

    ull acc[16];
    ull bias2 = dup2(bo[c]);
    #pragma unroll
    for (int i = 0; i < 16; ++i) acc[i] = bias2;

    #pragma unroll
    for (int l = 0; l < 3; ++l) {
        const float* hp = (l == 0 ? g_h0 : l == 1 ? g_h1 : g_h2) + (size_t)t*HB;
        const float* wp = Wo + (l*512)*On + c;
        #pragma unroll 2
        for (int d = 0; d < 512; ++d) {
            ull wv = dup2(wp[d*On]);
            const ulonglong2* h4 = reinterpret_cast<const ulonglong2*>(hp + d*64 + bh*32);
            #pragma unroll
            for (int q = 0; q < 8; ++q) {
                ulonglong2 hv = h4[q];
                fma2(acc[2*q],   hv.x, wv);
                fma2(acc[2*q+1], hv.y, wv);
            }
        }
    }
    #pragma unroll
    for (int i = 0; i < 16; ++i) {
        float lo, hi; unpack2(acc[i], lo, hi);
        int b = bh*32 + 2*i;
        out[(size_t)b     *(Tn*On) + t*On + c] = lo;
        out[(size_t)(b+1) *(Tn*On) + t*On + c] = hi;
    }
}

// =========================================================================
extern "C" void kernel_launch(void* const* d_in, const int* in_sizes, int n_in,
                              void* d_out, int out_size)
{
    const float* strokes = (const float*)d_in[0];
    const float* trans   = (const float*)d_in[1];
    const float* W0      = (const float*)d_in[2];
    const float* R0      = (const float*)d_in[3];
    const float* b0      = (const float*)d_in[4];
    const float* Wd      = (const float*)d_in[5];
    const float* bd      = (const float*)d_in[6];
    const float* W1      = (const float*)d_in[7];
    const float* R1      = (const float*)d_in[8];
    const float* b1      = (const float*)d_in[9];
    const float* W2      = (const float*)d_in[10];
    const float* R2      = (const float*)d_in[11];
    const float* b2      = (const float*)d_in[12];
    const float* Wo      = (const float*)d_in[13];
    const float* bo      = (const float*)d_in[14];

    float* out = (float*)d_out;
    float* att = out + (size_t)Bn * Tn * On;

    cudaFuncSetAttribute(k_scan01, cudaFuncAttributeMaxDynamicSharedMemorySize, SMEM_A);
    cudaFuncSetAttribute(k_scan2,  cudaFuncAttributeMaxDynamicSharedMemorySize, SMEM_S2);

    k_init<<<256, 256>>>(strokes);
    k_scan01<<<NGEMM + NATT, NTHR, SMEM_A>>>(trans, W0, R0, b0, Wd, bd,
                                             W1, R1, b1, att);
    k_scan2<<<NCTA, NTHR, SMEM_S2>>>(R2, W2, b2);
    k_out<<<Tn, 256>>>(Wo, bo, out);
}

// round 16
// speedup vs baseline: 1.1129x; 1.1129x over previous
#include <cuda_runtime.h>
#include <math.h>

#define Bn 64
#define Tn 800
#define Un 64
#define Nn 64
#define Kn 10
#define Hn 512
#define On 121
#define G4H 2048
#define HB (Hn*Bn)      /* 32768 */
#define NB (Nn*Bn)      /* 4096  */
#define NGEMM 128
#define NATT  16

typedef unsigned long long ull;

// Eigen/XLA-CPU pexp clamps its argument at ln(2^-126); replicate so the
// underflow tail ties bit-exactly (argmax -> 0) like the reference.
#define EXP_LO (-87.33654f)

// fused-scan SMEM layout (floats)
#define SW0_OFF 0                    /* 579*16  = 9264  */
#define SW1_OFF 9264                 /* 1091*16 = 17456 */
#define SW2_OFF (9264+17456)         /* 26720 */
#define SPA_OFF (26720+17456)        /* 44176: 8 slices * 1024 */
#define SZ_OFF  (SPA_OFF + 8192)     /* 52368 */
#define SMEM_A ((SZ_OFF + 1024) * 4) /* 213568 B */

// ---------------- device scratch (static, no allocations) ----------------
__device__ __align__(16) float g_h0[Tn*HB];          // [t][d][b]
__device__ __align__(16) float g_h1[Tn*HB];
__device__ __align__(16) float g_h2[Tn*HB];
__device__ __align__(16) float g_w [Tn*NB];          // [t][n][b]
__device__ __align__(16) float g_xT[Tn*3*Bn];        // [t][dim][b]
__device__ unsigned g_barc[4];                       // monotone barrier counters

// ---------------- fp32x2 helpers -----------------------------------------
__device__ __forceinline__ void fma2(ull &acc, ull a, ull b) {
    asm("fma.rn.f32x2 %0, %1, %2, %0;" : "+l"(acc) : "l"(a), "l"(b));
}
__device__ __forceinline__ void add2(ull &a, ull b) {
    asm("add.rn.f32x2 %0, %0, %1;" : "+l"(a) : "l"(b));
}
__device__ __forceinline__ ull dup2(float w) {
    ull r; asm("mov.b64 %0, {%1, %1};" : "=l"(r) : "f"(w)); return r;
}
__device__ __forceinline__ void unpack2(ull v, float &lo, float &hi) {
    asm("mov.b64 {%0, %1}, %2;" : "=f"(lo), "=f"(hi) : "l"(v));
}

// 8 cols x 4 batches accumulate: acc[2j]=(b0,b1), acc[2j+1]=(b2,b3) for col j
__device__ __forceinline__ void mac8(ull* acc, ulonglong2 in, float4 w0, float4 w1) {
    fma2(acc[0],  in.x, dup2(w0.x)); fma2(acc[1],  in.y, dup2(w0.x));
    fma2(acc[2],  in.x, dup2(w0.y)); fma2(acc[3],  in.y, dup2(w0.y));
    fma2(acc[4],  in.x, dup2(w0.z)); fma2(acc[5],  in.y, dup2(w0.z));
    fma2(acc[6],  in.x, dup2(w0.w)); fma2(acc[7],  in.y, dup2(w0.w));
    fma2(acc[8],  in.x, dup2(w1.x)); fma2(acc[9],  in.y, dup2(w1.x));
    fma2(acc[10], in.x, dup2(w1.y)); fma2(acc[11], in.y, dup2(w1.y));
    fma2(acc[12], in.x, dup2(w1.z)); fma2(acc[13], in.y, dup2(w1.z));
    fma2(acc[14], in.x, dup2(w1.w)); fma2(acc[15], in.y, dup2(w1.w));
}

// 32 distinct rows per warp, 8-deep LDG prefetch.
__device__ __forceinline__ void gemm_rows32(ull* acc, const float* __restrict__ gp,
                                            const float* __restrict__ wp) {
    ulonglong2 ib[8];
    #pragma unroll
    for (int i = 0; i < 8; ++i)
        ib[i] = *reinterpret_cast<const ulonglong2*>(gp + (size_t)i*64);
    #pragma unroll
    for (int c = 0; c < 4; ++c) {
        #pragma unroll
        for (int i = 0; i < 8; ++i) {
            int r = c*8 + i;
            float4 w0 = *reinterpret_cast<const float4*>(wp + r*16);
            float4 w1 = *reinterpret_cast<const float4*>(wp + r*16 + 4);
            ulonglong2 in = ib[i];
            if (c < 3)
                ib[i] = *reinterpret_cast<const ulonglong2*>(gp + (size_t)(r+8)*64);
            mac8(acc, in, w0, w1);
        }
    }
}

__device__ __forceinline__ void gemm_rowsN(ull* acc, const float* __restrict__ gp,
                                           const float* __restrict__ wp, int n) {
    #pragma unroll 4
    for (int r = 0; r < n; ++r) {
        ulonglong2 in = *reinterpret_cast<const ulonglong2*>(gp + (size_t)r*64);
        float4 w0 = *reinterpret_cast<const float4*>(wp + r*16);
        float4 w1 = *reinterpret_cast<const float4*>(wp + r*16 + 4);
        mac8(acc, in, w0, w1);
    }
}

// two-round partial store into 8 slices: warps 0..7 store, warps 8..15 add.
// sP layout: [slice 8][col 16][b 64]
__device__ __forceinline__ void store_partials2r(float* sP, int warp, int ch, int bg,
                                                 const ull* acc) {
    float* pp = sP + (warp & 7)*1024 + (ch*8)*64 + bg*4;
    if (warp < 8) {
        #pragma unroll
        for (int j = 0; j < 8; ++j)
            *reinterpret_cast<ulonglong2*>(pp + j*64) =
                make_ulonglong2(acc[2*j], acc[2*j+1]);
    }
    __syncthreads();
    if (warp >= 8) {
        #pragma unroll
        for (int j = 0; j < 8; ++j) {
            ulonglong2 m = *reinterpret_cast<ulonglong2*>(pp + j*64);
            add2(m.x, acc[2*j]); add2(m.y, acc[2*j+1]);
            *reinterpret_cast<ulonglong2*>(pp + j*64) = m;
        }
    }
    __syncthreads();
}

// 512-thread f32x2 tree reduce over 8 slices
__device__ __forceinline__ void reduce_pairs8(const float* sP, float* sZ, int tid) {
    int col = tid >> 5, b2 = tid & 31;
    const float* base = sP + col*64 + b2*2;
    ull v[8];
    #pragma unroll
    for (int k = 0; k < 8; ++k)
        v[k] = *reinterpret_cast<const ull*>(base + k*1024);
    ull s0 = v[0]; add2(s0, v[1]);
    ull s1 = v[2]; add2(s1, v[3]);
    ull s2 = v[4]; add2(s2, v[5]);
    ull s3 = v[6]; add2(s3, v[7]);
    add2(s0, s1); add2(s2, s3); add2(s0, s2);
    *reinterpret_cast<ull*>(sZ + col*64 + b2*2) = s0;
}

// fast gates (~1e-6 rel err)
__device__ __forceinline__ float sigf2(float x) {
    return __fdividef(1.f, 1.f + __expf(-x));
}
__device__ __forceinline__ float tanhf2(float x) {
    return 1.f - __fdividef(2.f, __expf(2.f*x) + 1.f);
}

// two-round store + reduce + gates + h store
__device__ __forceinline__ void reduce_gates(
    float* sP, float* sZ, int tid, int warp, int ch, int bg, const ull* acc,
    const float* sbL, float& creg, float* hout, int u0)
{
    store_partials2r(sP, warp, ch, bg, acc);
    reduce_pairs8(sP, sZ, tid);
    __syncthreads();
    if (tid < 256) {
        int uuR = tid >> 6, bR = tid & 63;
        float z[4];
        #pragma unroll
        for (int g = 0; g < 4; ++g)
            z[g] = sbL[uuR*4 + g] + sZ[(uuR*4 + g)*64 + bR];
        float cn = sigf2(z[1])*creg + sigf2(z[0])*tanhf2(z[2]);
        creg = cn;
        hout[(u0+uuR)*64 + bR] = sigf2(z[3])*tanhf2(cn);
    }
    __syncthreads();
}

// ---------------- release/acquire barrier primitives ---------------------
__device__ __forceinline__ void bar_arrive(int slot) {
    asm volatile("red.release.gpu.global.add.u32 [%0], 1;"
                 :: "l"(g_barc + slot) : "memory");
}
__device__ __forceinline__ void bar_wait_ge(int slot, unsigned target) {
    unsigned v;
    do {
        asm volatile("ld.acquire.gpu.global.u32 %0, [%1];"
                     : "=r"(v) : "l"(g_barc + slot) : "memory");
    } while (v < target);
}

// ---------------- init: barrier vars + stroke transpose ------------------
__global__ void k_init(const float* __restrict__ strokes) {
    int i = blockIdx.x * blockDim.x + threadIdx.x;
    int stride = gridDim.x * blockDim.x;
    for (int j = i; j < Tn*3*Bn; j += stride) {
        int t = j / 192, rem = j % 192, dim = rem / 64, b = rem & 63;
        g_xT[j] = strokes[b*(Tn*3) + t*3 + dim];
    }
    if (i < 4) g_barc[i] = 0u;
}

// =========================================================================
// Fully fused 3-layer scan + attention.  144 CTAs x 512 thr persistent.
//   CTA 0..127  : GEMM role. Tick t: L0 step t, L1 step t-1, L2 step t-2.
//   CTA 128..143: attention role (4 batches each).
// Slots: 0 = h0 (128/tick), 1 = w (16/tick), 2 = h1 (128), 3 = h2 (128).
// Every chip-wide wait is posted behind an independent ff-GEMM.
// =========================================================================
__global__ void __launch_bounds__(512, 1)
k_scan012(const float* __restrict__ trans,
          const float* __restrict__ W0, const float* __restrict__ R0,
          const float* __restrict__ b0, const float* __restrict__ Wd,
          const float* __restrict__ bd,
          const float* __restrict__ W1, const float* __restrict__ R1,
          const float* __restrict__ b1,
          const float* __restrict__ W2, const float* __restrict__ R2,
          const float* __restrict__ b2, float* __restrict__ attOut)
{
    extern __shared__ float sm[];
    const int tid  = threadIdx.x;
    const int lane = tid & 31;
    const int warp = tid >> 5;

    if (blockIdx.x < NGEMM) {
        // ================= GEMM role =================
        float* sW0 = sm + SW0_OFF;
        float* sW1 = sm + SW1_OFF;
        float* sW2 = sm + SW2_OFF;
        float* sP  = sm + SPA_OFF;
        float* sZ  = sm + SZ_OFF;
        __shared__ float sb[48];

        const int bg = lane & 15;
        const int ch = lane >> 4;
        const int u0 = blockIdx.x * 4;

        for (int idx = tid; idx < 579*16; idx += 512) {
            int r = idx >> 4, c = idx & 15;
            int col = (c & 3) * 512 + u0 + (c >> 2);
            float v;
            if (r < 512)      v = R0[r*G4H + col];
            else if (r < 576) v = W0[(3 + r - 512)*G4H + col];
            else              v = W0[(r - 576)*G4H + col];
            sW0[idx] = v;
        }
        for (int idx = tid; idx < 1091*16; idx += 512) {
            int r = idx >> 4, c = idx & 15;
            int col = (c & 3) * 512 + u0 + (c >> 2);
            float v1, v2;
            if (r < 512)       { v1 = R1[r*G4H + col];               v2 = R2[r*G4H + col]; }
            else if (r < 1024) { v1 = W1[(r - 512)*G4H + col];       v2 = W2[(r - 512)*G4H + col]; }
            else if (r < 1088) { v1 = W1[(512 + r - 1024)*G4H + col]; v2 = W2[(512 + r - 1024)*G4H + col]; }
            else               { v1 = W1[(576 + r - 1088)*G4H + col]; v2 = W2[(576 + r - 1088)*G4H + col]; }
            sW1[idx] = v1;
            sW2[idx] = v2;
        }
        if (tid < 16) {
            sb[tid]      = b0[(tid & 3) * 512 + u0 + (tid >> 2)];
            sb[16 + tid] = b1[(tid & 3) * 512 + u0 + (tid >> 2)];
            sb[32 + tid] = b2[(tid & 3) * 512 + u0 + (tid >> 2)];
        }
        __syncthreads();

        float c0 = 0.f, c1 = 0.f, c2s = 0.f;
        for (int t = 0; t <= Tn + 1; ++t) {
            // ---------- L0 step t ----------
            if (t < Tn) {
                ull acc[16];
                #pragma unroll
                for (int i = 0; i < 16; ++i) acc[i] = 0ull;
                if (t > 0)
                    gemm_rows32(acc, g_h0 + (size_t)(t-1)*HB + (warp*32)*64 + bg*4,
                                sW0 + (warp*32)*16 + ch*8);
                if (warp == 15)
                    gemm_rowsN(acc, g_xT + (size_t)t*192 + bg*4,
                               sW0 + 576*16 + ch*8, 3);
                if (tid == 0) bar_wait_ge(1, (unsigned)t * NATT);
                __syncthreads();
                if (t > 0)
                    gemm_rowsN(acc, g_w + (size_t)(t-1)*NB + (warp*4)*64 + bg*4,
                               sW0 + (512 + warp*4)*16 + ch*8, 4);
                reduce_gates(sP, sZ, tid, warp, ch, bg, acc,
                             sb, c0, g_h0 + (size_t)t*HB, u0);
                if (tid == 0) bar_arrive(0);     // S1: h0[t]
            } else if (t == Tn) {
                if (tid == 0) bar_wait_ge(1, (unsigned)Tn * NATT);
                __syncthreads();
            }

            if (t == 0) {
                if (tid == 0) bar_wait_ge(0, (unsigned)NGEMM);
                __syncthreads();
                continue;
            }

            // ---------- L1 step t-1 ----------
            if (t <= Tn) {
                const int s = t - 1;
                ull acc[16];
                #pragma unroll
                for (int i = 0; i < 16; ++i) acc[i] = 0ull;
                gemm_rows32(acc, g_h0 + (size_t)s*HB + (warp*32)*64 + bg*4,
                            sW1 + (512 + warp*32)*16 + ch*8);
                gemm_rowsN(acc, g_w + (size_t)s*NB + (warp*4)*64 + bg*4,
                           sW1 + (1024 + warp*4)*16 + ch*8, 4);
                if (warp == 15)
                    gemm_rowsN(acc, g_xT + (size_t)s*192 + bg*4,
                               sW1 + 1088*16 + ch*8, 3);
                // posted waits: S1 completion + h1[s-1] visibility
                if (tid == 0) {
                    if (t < Tn) bar_wait_ge(0, (unsigned)(t+1) * NGEMM);
                    if (s > 0)  bar_wait_ge(2, (unsigned)s * NGEMM);
                }
                __syncthreads();
                if (s > 0)
                    gemm_rows32(acc, g_h1 + (size_t)(s-1)*HB + (warp*32)*64 + bg*4,
                                sW1 + (warp*32)*16 + ch*8);
                reduce_gates(sP, sZ, tid, warp, ch, bg, acc,
                             sb + 16, c1, g_h1 + (size_t)s*HB, u0);
                if (tid == 0) bar_arrive(2);     // S3: h1[s]
            }

            // ---------- L2 step t-2 ----------
            if (t >= 2) {
                const int s2 = t - 2;
                if (t == Tn + 1) {
                    // no L1 block this tick posted the S3 wait; do it here
                    if (tid == 0) bar_wait_ge(2, (unsigned)Tn * NGEMM);
                    __syncthreads();
                }
                // h1[s2] visible: S3 >= (s2+1)*NGEMM = (t-1)*NGEMM, implied by
                // the L1 block's posted wait (s*NGEMM = (t-1)*NGEMM) above.
                ull acc[16];
                #pragma unroll
                for (int i = 0; i < 16; ++i) acc[i] = 0ull;
                gemm_rows32(acc, g_h1 + (size_t)s2*HB + (warp*32)*64 + bg*4,
                            sW2 + (512 + warp*32)*16 + ch*8);
                gemm_rowsN(acc, g_w + (size_t)s2*NB + (warp*4)*64 + bg*4,
                           sW2 + (1024 + warp*4)*16 + ch*8, 4);
                if (warp == 15)
                    gemm_rowsN(acc, g_xT + (size_t)s2*192 + bg*4,
                               sW2 + 1088*16 + ch*8, 3);
                if (tid == 0) {
                    if (s2 > 0) bar_wait_ge(3, (unsigned)s2 * NGEMM);
                }
                __syncthreads();
                if (s2 > 0)
                    gemm_rows32(acc, g_h2 + (size_t)(s2-1)*HB + (warp*32)*64 + bg*4,
                                sW2 + (warp*32)*16 + ch*8);
                reduce_gates(sP, sZ, tid, warp, ch, bg, acc,
                             sb + 32, c2s, g_h2 + (size_t)s2*HB, u0);
                if (tid == 0) bar_arrive(3);     // S4: h2[s2]
            }
        }
    } else {
        // ================= attention role =================
        float* sWd = sm;                    // 512*30 = 15360
        float* sTr = sm + 15360;            // 4*64*64 = 16384
        __shared__ float sPart[16*30*4];    // [w 16][c 30][b 4]
        __shared__ float sbd[30];
        __shared__ float sy[4*32];
        __shared__ float skap[4*16];
        __shared__ float swf[4*72];

        const int bb = (blockIdx.x - NGEMM) * 4;

        for (int idx = tid; idx < 512*30; idx += 512) sWd[idx] = Wd[idx];
        for (int i = 0; i < 32; ++i) {
            int idx = tid + i*512;
            int b_ = idx >> 12;
            sTr[idx] = trans[(bb + b_)*(Un*Nn) + (idx & 4095)];
        }
        if (tid < 30) sbd[tid] = bd[tid];
        if (tid < 64) skap[tid] = 0.f;
        __syncthreads();

        for (int t = 0; t < Tn; ++t) {
            if (tid == 0) bar_wait_ge(0, (unsigned)(t+1) * NGEMM);
            __syncthreads();

            // Wd matvec, coalesced broadcast reads of h0[t][d][bb..bb+3]
            {
                const float* hp = g_h0 + (size_t)t*HB + bb;
                const int d0 = warp*32;
                if (lane < 30) {
                    const float* wp = sWd + d0*30 + lane;
                    float a0 = 0.f, a1 = 0.f, a2 = 0.f, a3 = 0.f;
                    float4 hbuf[4];
                    #pragma unroll
                    for (int i = 0; i < 4; ++i)
                        hbuf[i] = *reinterpret_cast<const float4*>(hp + (d0+i)*64);
                    #pragma unroll
                    for (int r = 0; r < 32; ++r) {
                        float4 h = hbuf[r & 3];
                        if (r + 4 < 32)
                            hbuf[r & 3] = *reinterpret_cast<const float4*>(hp + (d0+r+4)*64);
                        float wv = wp[r*30];
                        a0 += h.x*wv; a1 += h.y*wv; a2 += h.z*wv; a3 += h.w*wv;
                    }
                    float* pp = sPart + (warp*30 + lane)*4;
                    pp[0] = a0; pp[1] = a1; pp[2] = a2; pp[3] = a3;
                }
            }
            __syncthreads();

            if (warp < 4) {
                int b_ = warp;
                if (lane < 30) {
                    float y = sbd[lane];
                    #pragma unroll
                    for (int s = 0; s < 16; ++s)
                        y += sPart[(s*30 + lane)*4 + b_];
                    sy[b_*32 + lane] = expf(y);
                }
                __syncwarp();
                if (lane < Kn) skap[b_*16 + lane] += sy[b_*32 + 20 + lane];
                __syncwarp();
            }
            __syncthreads();

            {
                int b_ = tid >> 7, u = tid & 127;
                if (u < Un + 1) {
                    float s = 0.f;
                    #pragma unroll
                    for (int k = 0; k < Kn; ++k) {
                        float dd  = skap[b_*16 + k] - (float)(u + 1);
                        float arg = -sy[b_*32 + 10 + k] * dd * dd;
                        if (arg < EXP_LO) arg = EXP_LO;   // Eigen pexp clamp
                        s += sy[b_*32 + k] * expf(arg);
                    }
                    swf[b_*72 + u] = s;
                }
            }
            __syncthreads();

            {
                int b_ = tid >> 7, n = tid & 127;
                if (n < Nn) {
                    const float* wf = swf + b_*72;
                    const float* tp = sTr + b_*4096 + n;
                    float acc2 = 0.f;
                    #pragma unroll 8
                    for (int u = 0; u < Un; ++u)
                        acc2 += wf[u] * tp[u*64];
                    g_w[(size_t)t*NB + n*64 + bb + b_] = acc2;
                } else if (n == 64) {
                    const float* wf = swf + b_*72;
                    float best = wf[0]; int bi = 0;
                    #pragma unroll 8
                    for (int u = 1; u < Un + 1; ++u)
                        if (wf[u] > best) { best = wf[u]; bi = u; }
                    attOut[(bb + b_)*Tn + t] = (float)bi;
                }
            }
            __syncthreads();
            if (tid == 0) bar_arrive(1);   // S2: w[t]
        }
    }
}

// =========================================================================
// Output GEMM: out[b][t][o] = [h0,h1,h2][t] @ Wo + bo   (grid = 800 CTAs)
// =========================================================================
__global__ void __launch_bounds__(256)
k_out(const float* __restrict__ Wo, const float* __restrict__ bo,
      float* __restrict__ out)
{
    const int t = blockIdx.x;
    const int tid = threadIdx.x;
    const int c = tid & 127;
    const int bh = tid >> 7;
    if (c >= On) return;

    ull acc[16];
    ull bias2 = dup2(bo[c]);
    #pragma unroll
    for (int i = 0; i < 16; ++i) acc[i] = bias2;

    #pragma unroll
    for (int l = 0; l < 3; ++l) {
        const float* hp = (l == 0 ? g_h0 : l == 1 ? g_h1 : g_h2) + (size_t)t*HB;
        const float* wp = Wo + (l*512)*On + c;
        #pragma unroll 2
        for (int d = 0; d < 512; ++d) {
            ull wv = dup2(wp[d*On]);
            const ulonglong2* h4 = reinterpret_cast<const ulonglong2*>(hp + d*64 + bh*32);
            #pragma unroll
            for (int q = 0; q < 8; ++q) {
                ulonglong2 hv = h4[q];
                fma2(acc[2*q],   hv.x, wv);
                fma2(acc[2*q+1], hv.y, wv);
            }
        }
    }
    #pragma unroll
    for (int i = 0; i < 16; ++i) {
        float lo, hi; unpack2(acc[i], lo, hi);
        int b = bh*32 + 2*i;
        out[(size_t)b     *(Tn*On) + t*On + c] = lo;
        out[(size_t)(b+1) *(Tn*On) + t*On + c] = hi;
    }
}

// =========================================================================
extern "C" void kernel_launch(void* const* d_in, const int* in_sizes, int n_in,
                              void* d_out, int out_size)
{
    const float* strokes = (const float*)d_in[0];
    const float* trans   = (const float*)d_in[1];
    const float* W0      = (const float*)d_in[2];
    const float* R0      = (const float*)d_in[3];
    const float* b0      = (const float*)d_in[4];
    const float* Wd      = (const float*)d_in[5];
    const float* bd      = (const float*)d_in[6];
    const float* W1      = (const float*)d_in[7];
    const float* R1      = (const float*)d_in[8];
    const float* b1      = (const float*)d_in[9];
    const float* W2      = (const float*)d_in[10];
    const float* R2      = (const float*)d_in[11];
    const float* b2      = (const float*)d_in[12];
    const float* Wo      = (const float*)d_in[13];
    const float* bo      = (const float*)d_in[14];

    float* out = (float*)d_out;
    float* att = out + (size_t)Bn * Tn * On;

    cudaFuncSetAttribute(k_scan012, cudaFuncAttributeMaxDynamicSharedMemorySize, SMEM_A);

    k_init<<<256, 256>>>(strokes);
    k_scan012<<<NGEMM + NATT, 512, SMEM_A>>>(trans, W0, R0, b0, Wd, bd,
                                             W1, R1, b1, W2, R2, b2, att);
    k_out<<<Tn, 256>>>(Wo, bo, out);
}

// round 17
// speedup vs baseline: 1.1607x; 1.0430x over previous
#include <cuda_runtime.h>
#include <math.h>

#define Bn 64
#define Tn 800
#define Un 64
#define Nn 64
#define Kn 10
#define Hn 512
#define On 121
#define G4H 2048
#define HB (Hn*Bn)      /* 32768 */
#define NB (Nn*Bn)      /* 4096  */
#define NGEMM 256       /* half-size GEMM CTAs (2 units each) */
#define NATT  16

typedef unsigned long long ull;

// Eigen/XLA-CPU pexp clamps its argument at ln(2^-126); replicate so the
// underflow tail ties bit-exactly (argmax -> 0) like the reference.
#define EXP_LO (-87.33654f)

// scan01 SMEM layout (floats): weights stride 8 cols
#define SW0_OFF 0                    /* 579*8  = 4632 */
#define SW1_OFF 4632                 /* 1091*8 = 8728 */
#define SPA_OFF (4632+8728)          /* 13360: 16 slices * 512 */
#define SZ_OFF  (SPA_OFF + 8192)     /* 21552 */
#define SMEM_A ((SZ_OFF + 512) * 4)  /* 88256 B */

// scan2 SMEM layout
#define SP2_OFF 8728
#define SZ2_OFF (SP2_OFF + 8192)
#define SMEM_S2 ((SZ2_OFF + 512) * 4) /* 69728 B */

// ---------------- device scratch (static, no allocations) ----------------
__device__ __align__(16) float g_h0[Tn*HB];          // [t][d][b]
__device__ __align__(16) float g_h1[Tn*HB];
__device__ __align__(16) float g_h2[Tn*HB];
__device__ __align__(16) float g_w [Tn*NB];          // [t][n][b]
__device__ __align__(16) float g_xT[Tn*3*Bn];        // [t][dim][b]
__device__ unsigned g_barc[4];                       // monotone barrier counters

// ---------------- fp32x2 helpers -----------------------------------------
__device__ __forceinline__ void fma2(ull &acc, ull a, ull b) {
    asm("fma.rn.f32x2 %0, %1, %2, %0;" : "+l"(acc) : "l"(a), "l"(b));
}
__device__ __forceinline__ void add2(ull &a, ull b) {
    asm("add.rn.f32x2 %0, %0, %1;" : "+l"(a) : "l"(b));
}
__device__ __forceinline__ ull dup2(float w) {
    ull r; asm("mov.b64 %0, {%1, %1};" : "=l"(r) : "f"(w)); return r;
}
__device__ __forceinline__ void unpack2(ull v, float &lo, float &hi) {
    asm("mov.b64 {%0, %1}, %2;" : "=f"(lo), "=f"(hi) : "l"(v));
}

// 8 cols x 4 batches accumulate: acc[2j]=(b0,b1), acc[2j+1]=(b2,b3) for col j
__device__ __forceinline__ void mac8(ull* acc, ulonglong2 in, float4 w0, float4 w1) {
    fma2(acc[0],  in.x, dup2(w0.x)); fma2(acc[1],  in.y, dup2(w0.x));
    fma2(acc[2],  in.x, dup2(w0.y)); fma2(acc[3],  in.y, dup2(w0.y));
    fma2(acc[4],  in.x, dup2(w0.z)); fma2(acc[5],  in.y, dup2(w0.z));
    fma2(acc[6],  in.x, dup2(w0.w)); fma2(acc[7],  in.y, dup2(w0.w));
    fma2(acc[8],  in.x, dup2(w1.x)); fma2(acc[9],  in.y, dup2(w1.x));
    fma2(acc[10], in.x, dup2(w1.y)); fma2(acc[11], in.y, dup2(w1.y));
    fma2(acc[12], in.x, dup2(w1.z)); fma2(acc[13], in.y, dup2(w1.z));
    fma2(acc[14], in.x, dup2(w1.w)); fma2(acc[15], in.y, dup2(w1.w));
}

// 32 distinct rows, 8-deep LDG prefetch; weight row stride WS floats.
template<int WS>
__device__ __forceinline__ void gemm_rows32(ull* acc, const float* __restrict__ gp,
                                            const float* __restrict__ wp) {
    ulonglong2 ib[8];
    #pragma unroll
    for (int i = 0; i < 8; ++i)
        ib[i] = *reinterpret_cast<const ulonglong2*>(gp + (size_t)i*64);
    #pragma unroll
    for (int c = 0; c < 4; ++c) {
        #pragma unroll
        for (int i = 0; i < 8; ++i) {
            int r = c*8 + i;
            float4 w0 = *reinterpret_cast<const float4*>(wp + r*WS);
            float4 w1 = *reinterpret_cast<const float4*>(wp + r*WS + 4);
            ulonglong2 in = ib[i];
            if (c < 3)
                ib[i] = *reinterpret_cast<const ulonglong2*>(gp + (size_t)(r+8)*64);
            mac8(acc, in, w0, w1);
        }
    }
}

template<int WS>
__device__ __forceinline__ void gemm_rowsN(ull* acc, const float* __restrict__ gp,
                                           const float* __restrict__ wp, int n) {
    #pragma unroll 4
    for (int r = 0; r < n; ++r) {
        ulonglong2 in = *reinterpret_cast<const ulonglong2*>(gp + (size_t)r*64);
        float4 w0 = *reinterpret_cast<const float4*>(wp + r*WS);
        float4 w1 = *reinterpret_cast<const float4*>(wp + r*WS + 4);
        mac8(acc, in, w0, w1);
    }
}

// sP layout: [slice 16][col 8][b 64]  (512 floats per slice)
__device__ __forceinline__ void store_partials(float* sP, int slice, int bg,
                                               const ull* acc) {
    float* pp = sP + slice*512 + bg*4;
    #pragma unroll
    for (int j = 0; j < 8; ++j)
        *reinterpret_cast<ulonglong2*>(pp + j*64) =
            make_ulonglong2(acc[2*j], acc[2*j+1]);
}

// 256-thread f32x2 tree reduce over 16 slices (same tree as scalar reduce16)
__device__ __forceinline__ void reduce_pairs(const float* sP, float* sZ, int tid) {
    int col = tid >> 5, b2 = tid & 31;     // col 0..7
    const float* base = sP + col*64 + b2*2;
    ull v[16];
    #pragma unroll
    for (int k = 0; k < 16; ++k)
        v[k] = *reinterpret_cast<const ull*>(base + k*512);
    ull s0 = v[0];  add2(s0, v[1]);  ull t0 = v[8];  add2(t0, v[9]);  add2(s0, t0);
    ull s1 = v[2];  add2(s1, v[3]);  ull t1 = v[10]; add2(t1, v[11]); add2(s1, t1);
    ull s2 = v[4];  add2(s2, v[5]);  ull t2 = v[12]; add2(t2, v[13]); add2(s2, t2);
    ull s3 = v[6];  add2(s3, v[7]);  ull t3 = v[14]; add2(t3, v[15]); add2(s3, t3);
    add2(s0, s1); add2(s2, s3); add2(s0, s2);
    *reinterpret_cast<ull*>(sZ + col*64 + b2*2) = s0;
}

// fast gates (~1e-6 rel err)
__device__ __forceinline__ float sigf2(float x) {
    return __fdividef(1.f, 1.f + __expf(-x));
}
__device__ __forceinline__ float tanhf2(float x) {
    return 1.f - __fdividef(2.f, __expf(2.f*x) + 1.f);
}

// store + reduce (256 thr) + gates (128 thr) + h store
__device__ __forceinline__ void reduce_gates(
    float* sP, float* sZ, int tid, int slice, int bg, const ull* acc,
    const float* sbL, float& creg, float* hout, int u0)
{
    store_partials(sP, slice, bg, acc);
    __syncthreads();
    reduce_pairs(sP, sZ, tid);
    __syncthreads();
    if (tid < 128) {
        int uu = tid >> 6, bR = tid & 63;
        float z[4];
        #pragma unroll
        for (int g = 0; g < 4; ++g)
            z[g] = sbL[uu*4 + g] + sZ[(uu*4 + g)*64 + bR];
        float cn = sigf2(z[1])*creg + sigf2(z[0])*tanhf2(z[2]);
        creg = cn;
        hout[(u0+uu)*64 + bR] = sigf2(z[3])*tanhf2(cn);
    }
    __syncthreads();
}

// ---------------- release/acquire barrier primitives ---------------------
__device__ __forceinline__ void bar_arrive(int slot) {
    asm volatile("red.release.gpu.global.add.u32 [%0], 1;"
                 :: "l"(g_barc + slot) : "memory");
}
__device__ __forceinline__ void bar_wait_ge(int slot, unsigned target) {
    unsigned v;
    do {
        asm volatile("ld.acquire.gpu.global.u32 %0, [%1];"
                     : "=r"(v) : "l"(g_barc + slot) : "memory");
    } while (v < target);
}

// ---------------- init: barrier vars + stroke transpose ------------------
__global__ void k_init(const float* __restrict__ strokes) {
    int i = blockIdx.x * blockDim.x + threadIdx.x;
    int stride = gridDim.x * blockDim.x;
    for (int j = i; j < Tn*3*Bn; j += stride) {
        int t = j / 192, rem = j % 192, dim = rem / 64, b = rem & 63;
        g_xT[j] = strokes[b*(Tn*3) + t*3 + dim];
    }
    if (i < 4) g_barc[i] = 0u;
}

// =========================================================================
// Fused L0+L1 scan + attention.  272 CTAs x 256 thr persistent, 2 CTAs/SM.
//   CTA 0..255  : GEMM role, 2 units each. Tick t: L0 step t, L1 step t-1.
//                 warp w: strips 2w (lanes 0-15) and 2w+1 (lanes 16-31).
//   CTA 256..271: attention role (4 batches; Wd/trans L1-resident global).
// Slots: 0 = h0 (256/tick), 1 = w (16/tick), 2 = h1 (256/tick).
// =========================================================================
__global__ void __launch_bounds__(256, 2)
k_scan01(const float* __restrict__ trans,
         const float* __restrict__ W0, const float* __restrict__ R0,
         const float* __restrict__ b0, const float* __restrict__ Wd,
         const float* __restrict__ bd,
         const float* __restrict__ W1, const float* __restrict__ R1,
         const float* __restrict__ b1, float* __restrict__ attOut)
{
    extern __shared__ float sm[];
    __shared__ float sb[16];
    __shared__ float sPart[16*30*4];    // att: [slice 16][c 30][b 4]
    __shared__ float sbd[30];
    __shared__ float sy[4*32];
    __shared__ float skap[4*16];
    __shared__ float swf[4*72];

    const int tid  = threadIdx.x;
    const int lane = tid & 31;
    const int warp = tid >> 5;

    if (blockIdx.x < NGEMM) {
        // ================= GEMM role =================
        float* sW0 = sm + SW0_OFF;
        float* sW1 = sm + SW1_OFF;
        float* sP  = sm + SPA_OFF;
        float* sZ  = sm + SZ_OFF;

        const int bg    = lane & 15;
        const int st    = lane >> 4;
        const int slice = warp*2 + st;      // 0..15
        const int u0    = blockIdx.x * 2;   // 2 units

        for (int idx = tid; idx < 579*8; idx += 256) {
            int r = idx >> 3, c = idx & 7;
            int col = (c & 3) * 512 + u0 + (c >> 2);
            float v;
            if (r < 512)      v = R0[r*G4H + col];
            else if (r < 576) v = W0[(3 + r - 512)*G4H + col];
            else              v = W0[(r - 576)*G4H + col];
            sW0[idx] = v;
        }
        for (int idx = tid; idx < 1091*8; idx += 256) {
            int r = idx >> 3, c = idx & 7;
            int col = (c & 3) * 512 + u0 + (c >> 2);
            float v;
            if (r < 512)       v = R1[r*G4H + col];
            else if (r < 1024) v = W1[(r - 512)*G4H + col];
            else if (r < 1088) v = W1[(512 + r - 1024)*G4H + col];
            else               v = W1[(576 + r - 1088)*G4H + col];
            sW1[idx] = v;
        }
        if (tid < 8) {
            sb[tid]     = b0[(tid & 3) * 512 + u0 + (tid >> 2)];
            sb[8 + tid] = b1[(tid & 3) * 512 + u0 + (tid >> 2)];
        }
        __syncthreads();

        float c0 = 0.f, c1 = 0.f;
        for (int t = 0; t <= Tn; ++t) {
            // ---------- L0 step t ----------
            if (t < Tn) {
                ull acc[16];
                #pragma unroll
                for (int i = 0; i < 16; ++i) acc[i] = 0ull;
                if (t > 0)
                    gemm_rows32<8>(acc, g_h0 + (size_t)(t-1)*HB + (slice*32)*64 + bg*4,
                                   sW0 + (slice*32)*8);
                if (slice == 15)
                    gemm_rowsN<8>(acc, g_xT + (size_t)t*192 + bg*4, sW0 + 576*8, 3);
                if (tid == 0) bar_wait_ge(1, (unsigned)t * NATT);
                __syncthreads();
                if (t > 0)
                    gemm_rowsN<8>(acc, g_w + (size_t)(t-1)*NB + (slice*4)*64 + bg*4,
                                  sW0 + (512 + slice*4)*8, 4);
                reduce_gates(sP, sZ, tid, slice, bg, acc,
                             sb, c0, g_h0 + (size_t)t*HB, u0);
                if (tid == 0) bar_arrive(0);     // S1: h0[t]
            } else {
                if (tid == 0) bar_wait_ge(1, (unsigned)Tn * NATT);
                __syncthreads();
            }

            if (t == 0) {
                if (tid == 0) bar_wait_ge(0, (unsigned)NGEMM);
                __syncthreads();
                continue;
            }

            // ---------- L1 step t-1 (both chip waits posted behind ff) ----
            {
                const int s = t - 1;
                ull acc[16];
                #pragma unroll
                for (int i = 0; i < 16; ++i) acc[i] = 0ull;
                gemm_rows32<8>(acc, g_h0 + (size_t)s*HB + (slice*32)*64 + bg*4,
                               sW1 + (512 + slice*32)*8);
                gemm_rowsN<8>(acc, g_w + (size_t)s*NB + (slice*4)*64 + bg*4,
                              sW1 + (1024 + slice*4)*8, 4);
                if (slice == 15)
                    gemm_rowsN<8>(acc, g_xT + (size_t)s*192 + bg*4,
                                  sW1 + 1088*8, 3);
                if (tid == 0) {
                    if (t < Tn) bar_wait_ge(0, (unsigned)(t+1) * NGEMM);
                    if (s > 0)  bar_wait_ge(2, (unsigned)s * NGEMM);
                }
                __syncthreads();
                if (s > 0)
                    gemm_rows32<8>(acc, g_h1 + (size_t)(s-1)*HB + (slice*32)*64 + bg*4,
                                   sW1 + (slice*32)*8);
                reduce_gates(sP, sZ, tid, slice, bg, acc,
                             sb + 8, c1, g_h1 + (size_t)s*HB, u0);
                if (tid == 0) bar_arrive(2);     // S3: h1[s]
            }
        }
    } else {
        // ================= attention role (Wd/trans via L1-resident LDG) ==
        const int bb = (blockIdx.x - NGEMM) * 4;
        if (tid < 30) sbd[tid] = bd[tid];
        if (tid < 64) skap[tid] = 0.f;
        __syncthreads();

        for (int t = 0; t < Tn; ++t) {
            if (tid == 0) bar_wait_ge(0, (unsigned)(t+1) * NGEMM);
            __syncthreads();

            // Wd matvec: warp w covers d [64w, 64w+64) as two 32-row strips
            // (keeps the 16-partial y-sum order bit-identical).
            if (lane < 30) {
                const float* hp = g_h0 + (size_t)t*HB + bb;
                #pragma unroll
                for (int sseg = 0; sseg < 2; ++sseg) {
                    const int d0 = warp*64 + sseg*32;
                    const float* wp = Wd + d0*30 + lane;
                    float a0 = 0.f, a1 = 0.f, a2 = 0.f, a3 = 0.f;
                    float4 hbuf[4];
                    #pragma unroll
                    for (int i = 0; i < 4; ++i)
                        hbuf[i] = *reinterpret_cast<const float4*>(hp + (d0+i)*64);
                    #pragma unroll
                    for (int r = 0; r < 32; ++r) {
                        float4 h = hbuf[r & 3];
                        if (r + 4 < 32)
                            hbuf[r & 3] = *reinterpret_cast<const float4*>(hp + (d0+r+4)*64);
                        float wv = wp[r*30];
                        a0 += h.x*wv; a1 += h.y*wv; a2 += h.z*wv; a3 += h.w*wv;
                    }
                    float* pp = sPart + ((warp*2 + sseg)*30 + lane)*4;
                    pp[0] = a0; pp[1] = a1; pp[2] = a2; pp[3] = a3;
                }
            }
            __syncthreads();

            if (warp < 4) {
                int b_ = warp;
                if (lane < 30) {
                    float y = sbd[lane];
                    #pragma unroll
                    for (int s = 0; s < 16; ++s)
                        y += sPart[(s*30 + lane)*4 + b_];
                    sy[b_*32 + lane] = expf(y);
                }
                __syncwarp();
                if (lane < Kn) skap[b_*16 + lane] += sy[b_*32 + 20 + lane];
                __syncwarp();
            }
            __syncthreads();

            // phi: u 0..63 over all 4 batches; u=64 by threads 0..3
            {
                int b_ = tid >> 6, u = tid & 63;
                float s = 0.f;
                #pragma unroll
                for (int k = 0; k < Kn; ++k) {
                    float dd  = skap[b_*16 + k] - (float)(u + 1);
                    float arg = -sy[b_*32 + 10 + k] * dd * dd;
                    if (arg < EXP_LO) arg = EXP_LO;   // Eigen pexp clamp
                    s += sy[b_*32 + k] * expf(arg);
                }
                swf[b_*72 + u] = s;
            }
            if (tid < 4) {
                int b_ = tid; const int u = 64;
                float s = 0.f;
                #pragma unroll
                for (int k = 0; k < Kn; ++k) {
                    float dd  = skap[b_*16 + k] - (float)(u + 1);
                    float arg = -sy[b_*32 + 10 + k] * dd * dd;
                    if (arg < EXP_LO) arg = EXP_LO;
                    s += sy[b_*32 + k] * expf(arg);
                }
                swf[b_*72 + u] = s;
            }
            __syncthreads();

            // w2: 4 batches x 64 n = 256 threads
            {
                int b_ = tid >> 6, n = tid & 63;
                const float* wf = swf + b_*72;
                const float* tp = trans + (size_t)(bb + b_)*(Un*Nn) + n;
                float acc2 = 0.f;
                #pragma unroll 8
                for (int u = 0; u < Un; ++u)
                    acc2 += wf[u] * tp[u*64];
                g_w[(size_t)t*NB + n*64 + bb + b_] = acc2;
            }
            if (tid < 4) {
                const float* wf = swf + tid*72;
                float best = wf[0]; int bi = 0;
                #pragma unroll 8
                for (int u = 1; u < Un + 1; ++u)
                    if (wf[u] > best) { best = wf[u]; bi = u; }
                attOut[(bb + tid)*Tn + t] = (float)bi;
            }
            __syncthreads();
            if (tid == 0) bar_arrive(1);   // S2: w[t]
        }
    }
}

// =========================================================================
// L2 scan: 256 CTAs x 256 thr, 2 CTAs/SM. ff of t+1 posted behind barrier.
// =========================================================================
__global__ void __launch_bounds__(256, 2)
k_scan2(const float* __restrict__ R, const float* __restrict__ W,
        const float* __restrict__ bias)
{
    extern __shared__ float sm[];
    float* sW = sm;                  // 1091*8 = 8728
    float* sP = sm + SP2_OFF;
    float* sZ = sm + SZ2_OFF;
    __shared__ float sb[8];

    const float* hin = g_h1;
    float* hseq      = g_h2;
    const int slot = 3;
    const int tid  = threadIdx.x;
    const int lane = tid & 31;
    const int warp = tid >> 5;
    const int bg    = lane & 15;
    const int st    = lane >> 4;
    const int slice = warp*2 + st;
    const int u0    = blockIdx.x * 2;

    for (int idx = tid; idx < 1091*8; idx += 256) {
        int r = idx >> 3, c = idx & 7;
        int col = (c & 3) * 512 + u0 + (c >> 2);
        float v;
        if (r < 512)       v = R[r*G4H + col];
        else if (r < 1024) v = W[(r - 512)*G4H + col];
        else if (r < 1088) v = W[(512 + r - 1024)*G4H + col];
        else               v = W[(576 + r - 1088)*G4H + col];
        sW[idx] = v;
    }
    if (tid < 8) sb[tid] = bias[(tid & 3) * 512 + u0 + (tid >> 2)];
    float creg = 0.f;
    __syncthreads();

    ull acc[16];
    #pragma unroll
    for (int i = 0; i < 16; ++i) acc[i] = 0ull;
    gemm_rows32<8>(acc, hin + (slice*32)*64 + bg*4, sW + (512 + slice*32)*8);
    gemm_rowsN<8>(acc, g_w + (slice*4)*64 + bg*4, sW + (1024 + slice*4)*8, 4);
    if (slice == 15)
        gemm_rowsN<8>(acc, g_xT + bg*4, sW + 1088*8, 3);

    for (int t = 0; t < Tn; ++t) {
        if (t > 0)
            gemm_rows32<8>(acc, hseq + (size_t)(t-1)*HB + (slice*32)*64 + bg*4,
                           sW + (slice*32)*8);

        store_partials(sP, slice, bg, acc);
        __syncthreads();
        reduce_pairs(sP, sZ, tid);
        __syncthreads();
        if (tid < 128) {
            int uu = tid >> 6, bR = tid & 63;
            float z[4];
            #pragma unroll
            for (int g = 0; g < 4; ++g)
                z[g] = sb[uu*4 + g] + sZ[(uu*4 + g)*64 + bR];
            float cn = sigf2(z[1])*creg + sigf2(z[0])*tanhf2(z[2]);
            creg = cn;
            hseq[(size_t)t*HB + (u0+uu)*64 + bR] = sigf2(z[3])*tanhf2(cn);
        }
        __syncthreads();
        if (tid == 0) bar_arrive(slot);

        #pragma unroll
        for (int i = 0; i < 16; ++i) acc[i] = 0ull;
        if (t < Tn - 1) {
            gemm_rows32<8>(acc, hin + (size_t)(t+1)*HB + (slice*32)*64 + bg*4,
                           sW + (512 + slice*32)*8);
            gemm_rowsN<8>(acc, g_w + (size_t)(t+1)*NB + (slice*4)*64 + bg*4,
                          sW + (1024 + slice*4)*8, 4);
            if (slice == 15)
                gemm_rowsN<8>(acc, g_xT + (size_t)(t+1)*192 + bg*4,
                              sW + 1088*8, 3);
        }
        if (tid == 0) bar_wait_ge(slot, (unsigned)(t+1) * NGEMM);
        __syncthreads();
    }
}

// =========================================================================
// Output GEMM: out[b][t][o] = [h0,h1,h2][t] @ Wo + bo   (grid = 800 CTAs)
// =========================================================================
__global__ void __launch_bounds__(256)
k_out(const float* __restrict__ Wo, const float* __restrict__ bo,
      float* __restrict__ out)
{
    const int t = blockIdx.x;
    const int tid = threadIdx.x;
    const int c = tid & 127;
    const int bh = tid >> 7;
    if (c >= On) return;

    ull acc[16];
    ull bias2 = dup2(bo[c]);
    #pragma unroll
    for (int i = 0; i < 16; ++i) acc[i] = bias2;

    #pragma unroll
    for (int l = 0; l < 3; ++l) {
        const float* hp = (l == 0 ? g_h0 : l == 1 ? g_h1 : g_h2) + (size_t)t*HB;
        const float* wp = Wo + (l*512)*On + c;
        #pragma unroll 2
        for (int d = 0; d < 512; ++d) {
            ull wv = dup2(wp[d*On]);
            const ulonglong2* h4 = reinterpret_cast<const ulonglong2*>(hp + d*64 + bh*32);
            #pragma unroll
            for (int q = 0; q < 8; ++q) {
                ulonglong2 hv = h4[q];
                fma2(acc[2*q],   hv.x, wv);
                fma2(acc[2*q+1], hv.y, wv);
            }
        }
    }
    #pragma unroll
    for (int i = 0; i < 16; ++i) {
        float lo, hi; unpack2(acc[i], lo, hi);
        int b = bh*32 + 2*i;
        out[(size_t)b     *(Tn*On) + t*On + c] = lo;
        out[(size_t)(b+1) *(Tn*On) + t*On + c] = hi;
    }
}

// =========================================================================
extern "C" void kernel_launch(void* const* d_in, const int* in_sizes, int n_in,
                              void* d_out, int out_size)
{
    const float* strokes = (const float*)d_in[0];
    const float* trans   = (const float*)d_in[1];
    const float* W0      = (const float*)d_in[2];
    const float* R0      = (const float*)d_in[3];
    const float* b0      = (const float*)d_in[4];
    const float* Wd      = (const float*)d_in[5];
    const float* bd      = (const float*)d_in[6];
    const float* W1      = (const float*)d_in[7];
    const float* R1      = (const float*)d_in[8];
    const float* b1      = (const float*)d_in[9];
    const float* W2      = (const float*)d_in[10];
    const float* R2      = (const float*)d_in[11];
    const float* b2      = (const float*)d_in[12];
    const float* Wo      = (const float*)d_in[13];
    const float* bo      = (const float*)d_in[14];

    float* out = (float*)d_out;
    float* att = out + (size_t)Bn * Tn * On;

    cudaFuncSetAttribute(k_scan01, cudaFuncAttributeMaxDynamicSharedMemorySize, SMEM_A);
    cudaFuncSetAttribute(k_scan2,  cudaFuncAttributeMaxDynamicSharedMemorySize, SMEM_S2);

    k_init<<<256, 256>>>(strokes);
    k_scan01<<<NGEMM + NATT, 256, SMEM_A>>>(trans, W0, R0, b0, Wd, bd,
                                            W1, R1, b1, att);
    k_scan2<<<NGEMM, 256, SMEM_S2>>>(R2, W2, b2);
    k_out<<<Tn, 256>>>(Wo, bo, out);
}